// round 14
// baseline (speedup 1.0000x reference)
#include <cuda_runtime.h>

// CoincidenceLIFBank: B=32 x T=4096 x D=256.
// Output: [0,B*D) pooled | [B*D,+B*D*T) spikes | +D rw | +D tw | +D beta
//
// NUMERICS FROZEN (rel_err 9.894e-4 across R6-R13):
//   rw/tw = max(x,0) + logf(1 + expf(-|x|));  sigmoid = 1/(1+expf(-x))
//   beta  = fadd(0.7, fmul(0.295, sigmoid))         (uncontracted)
//   cur   = fadd(fmul(rw, rv), fmul(tw, tv))        (UNcontracted)
//   mp    = fma(beta, m, cur); ms = fadd(mp,-1); p = (mp>=1)
//   m = p ? ms : mp;  s = p ? 1 : 0
// OOB ref reads exact 0.0f from the zero-padded smem row. cur is computed
// with the identical op sequence -- just on a different warp.
//
// R14: warp specialization. Per block (1 per SM): 2 CHAIN warps (pure serial
// LIF recurrence, ~7 issue/step vs the 12-cyc dependence floor) + 2 PRODUCER
// warps (cur precompute into double-buffered smem tiles + coalesced spike
// dump). Pairwise named-barrier handoff per 128-step tile.

#define NB 32
#define NT 4096
#define ND 256
#define THRESH 1.0f
#define TILE 128
#define NTILES (NT / TILE)
#define TSTRIDE 132                 // floats per tile row (528B, 16B-aligned)
#define SREF_N (NT + 256)           // zero pad: delay<128 + slack

#define CURSZ (32 * TSTRIDE)        // one cur/sp buffer (4224 floats)
#define OFF_SREF 0
#define OFF_STGT SREF_N
#define OFF_CUR  (SREF_N + NT)          // cur[group][buf] : 4 buffers
#define OFF_SP   (OFF_CUR + 4 * CURSZ) // sp [group][buf] : 4 buffers
#define SMEM_FLOATS (OFF_SP + 4 * CURSZ)
#define SMEM_BYTES  (SMEM_FLOATS * 4)   // 168,960 B

__device__ __forceinline__ float softplus_xla(float x) {
    const float u = expf(-fabsf(x));
    return __fadd_rn(fmaxf(x, 0.0f), logf(__fadd_rn(1.0f, u)));
}
__device__ __forceinline__ float sigmoid_xla(float x) {
    return 1.0f / (__fadd_rn(1.0f, expf(-x)));
}
__device__ __forceinline__ void bar64(int id) {
    asm volatile("bar.sync %0, %1;" :: "r"(id), "r"(64) : "memory");
}

__global__ void __launch_bounds__(128, 1)
lif_bank_kernel(const float* __restrict__ ref,
                const float* __restrict__ tgt,
                const int*   __restrict__ delays,
                const float* __restrict__ rw_raw,
                const float* __restrict__ tw_raw,
                const float* __restrict__ beta_raw,
                float* __restrict__ out)
{
    extern __shared__ float smem[];
    float* __restrict__ sref = smem + OFF_SREF;
    float* __restrict__ stgt = smem + OFF_STGT;

    const int tid  = threadIdx.x;
    const int wid  = tid >> 5;
    const int lane = tid & 31;
    const int b    = blockIdx.x >> 2;     // 32 batches
    const int q    = blockIdx.x & 3;      // 4 groups of 64 delays
    const int role = wid >> 1;            // 0 = chain, 1 = producer
    const int g    = wid & 1;             // delay subgroup within block
    const int d    = q * 64 + g * 32 + lane;

    float* __restrict__ curb0 = smem + OFF_CUR + (2 * g + 0) * CURSZ;
    float* __restrict__ curb1 = smem + OFF_CUR + (2 * g + 1) * CURSZ;
    float* __restrict__ spb0  = smem + OFF_SP  + (2 * g + 0) * CURSZ;
    float* __restrict__ spb1  = smem + OFF_SP  + (2 * g + 1) * CURSZ;

    // ---- cooperative staging of ref[b,:] (+zero pad) and tgt[b,:] ----
    {
        const float4* __restrict__ ref4 = (const float4*)(ref + b * NT);
        const float4* __restrict__ tgt4 = (const float4*)(tgt + b * NT);
        float4* sr4 = (float4*)sref;
        float4* st4 = (float4*)stgt;
#pragma unroll 2
        for (int i = tid; i < NT / 4; i += 128) {
            sr4[i] = __ldg(ref4 + i);
            st4[i] = __ldg(tgt4 + i);
        }
        for (int i = NT / 4 + tid; i < SREF_N / 4; i += 128)
            sr4[i] = make_float4(0.f, 0.f, 0.f, 0.f);
    }
    __syncthreads();

    float* out_pooled = out;
    float* out_spk    = out + NB * ND;
    float* out_rw     = out + NB * ND + (size_t)NB * ND * NT;
    float* out_tw     = out_rw + ND;
    float* out_beta   = out_tw + ND;

    const int barid = 1 + g;

    if (role == 1) {
        // ================= PRODUCER warp =================
        const float rw    = softplus_xla(rw_raw[d]);
        const float tw    = softplus_xla(tw_raw[d]);
        const int   delay = delays[d];

        // pre-fill tile 0 into buffer 0
        {
#pragma unroll 4
            for (int tt = 0; tt < TILE; tt += 4) {
                const float4 v = *(const float4*)(stgt + tt);
                const float tv[4] = {v.x, v.y, v.z, v.w};
                float c[4];
#pragma unroll
                for (int j = 0; j < 4; j++) {
                    const float rv = sref[delay + tt + j];
                    c[j] = __fadd_rn(__fmul_rn(rw, rv), __fmul_rn(tw, tv[j]));
                }
                *(float4*)&curb0[lane * TSTRIDE + tt] =
                    make_float4(c[0], c[1], c[2], c[3]);
            }
        }
        bar64(barid);

        for (int k = 0; k < NTILES; k++) {
            // fill cur for tile k+1 into buffer !(k&1)
            if (k + 1 < NTILES) {
                float* curN = (k & 1) ? curb0 : curb1;
                const int t0 = (k + 1) * TILE;
#pragma unroll 4
                for (int tt = 0; tt < TILE; tt += 4) {
                    const float4 v = *(const float4*)(stgt + t0 + tt);
                    const float tv[4] = {v.x, v.y, v.z, v.w};
                    float c[4];
#pragma unroll
                    for (int j = 0; j < 4; j++) {
                        const float rv = sref[delay + t0 + tt + j];
                        c[j] = __fadd_rn(__fmul_rn(rw, rv), __fmul_rn(tw, tv[j]));
                    }
                    *(float4*)&curN[lane * TSTRIDE + tt] =
                        make_float4(c[0], c[1], c[2], c[3]);
                }
            }
            // dump spikes of tile k-1 from buffer !(k&1)
            if (k >= 1) {
                float* spN = (k & 1) ? spb0 : spb1;
                const int t0 = (k - 1) * TILE;
#pragma unroll 2
                for (int r = 0; r < 32; r++) {
                    const float4 w = *(const float4*)&spN[r * TSTRIDE + lane * 4];
                    float* dst = out_spk +
                        (size_t)(b * ND + q * 64 + g * 32 + r) * NT + t0;
                    *(float4*)(dst + lane * 4) = w;
                }
            }
            bar64(barid);
        }

        // final dump: tile NTILES-1 lives in buffer (NTILES-1)&1 = 1
        {
            const int t0 = (NTILES - 1) * TILE;
#pragma unroll 2
            for (int r = 0; r < 32; r++) {
                const float4 w = *(const float4*)&spb1[r * TSTRIDE + lane * 4];
                float* dst = out_spk +
                    (size_t)(b * ND + q * 64 + g * 32 + r) * NT + t0;
                *(float4*)(dst + lane * 4) = w;
            }
        }

        if (b == 0) { out_rw[d] = rw; out_tw[d] = tw; }
    } else {
        // ================= CHAIN warp =================
        const float beta = __fadd_rn(0.7f,
                            __fmul_rn(0.295f, sigmoid_xla(beta_raw[d])));
        float m = 0.0f;
        int   cnt = 0;

        bar64(barid);   // wait for tile-0 cur

        for (int k = 0; k < NTILES; k++) {
            float* __restrict__ curb = (k & 1) ? curb1 : curb0;
            float* __restrict__ spb  = (k & 1) ? spb1  : spb0;

            // prefetch first group, then ping through the tile
            float4 c4 = *(const float4*)&curb[lane * TSTRIDE];
#pragma unroll 4
            for (int tt = 0; tt < TILE; tt += 4) {
                const float4 n4 = *(const float4*)
                    &curb[lane * TSTRIDE + ((tt + 4) & (TILE - 1))];
                const float cu[4] = {c4.x, c4.y, c4.z, c4.w};
                float s[4];
#pragma unroll
                for (int j = 0; j < 4; j++) {
                    const float mp = __fmaf_rn(beta, m, cu[j]);
                    const float ms = __fadd_rn(mp, -THRESH);
                    const bool  p  = (mp >= THRESH);
                    m = p ? ms : mp;
                    s[j] = p ? 1.0f : 0.0f;
                    cnt += p ? 1 : 0;
                }
                *(float4*)&spb[lane * TSTRIDE + tt] =
                    make_float4(s[0], s[1], s[2], s[3]);
                c4 = n4;
            }
            bar64(barid);
        }

        out_pooled[b * ND + d] = (float)cnt * (1.0f / NT);
        if (b == 0) out_beta[d] = beta;
    }
}

extern "C" void kernel_launch(void* const* d_in, const int* in_sizes, int n_in,
                              void* d_out, int out_size)
{
    const float* ref      = (const float*)d_in[0];
    const float* tgt      = (const float*)d_in[1];
    const int*   delays   = (const int*)  d_in[2];
    const float* rw_raw   = (const float*)d_in[3];
    const float* tw_raw   = (const float*)d_in[4];
    const float* beta_raw = (const float*)d_in[5];
    float* out = (float*)d_out;

    cudaFuncSetAttribute(lif_bank_kernel,
                         cudaFuncAttributeMaxDynamicSharedMemorySize,
                         SMEM_BYTES);

    // 128 blocks x 128 threads: per block 2 chain warps + 2 producer warps,
    // one block per SM, each warp on its own SMSP.
    lif_bank_kernel<<<NB * 4, 128, SMEM_BYTES>>>(ref, tgt, delays, rw_raw,
                                                 tw_raw, beta_raw, out);
}

// round 15
// speedup vs baseline: 1.0004x; 1.0004x over previous
#include <cuda_runtime.h>

// CoincidenceLIFBank: B=32 x T=4096 x D=256.
// Output: [0,B*D) pooled | [B*D,+B*D*T) spikes | +D rw | +D tw | +D beta
//
// NUMERICS FROZEN (rel_err 9.894e-4 across R6-R13):
//   rw/tw = max(x,0) + logf(1 + expf(-|x|));  sigmoid = 1/(1+expf(-x))
//   beta  = fadd(0.7, fmul(0.295, sigmoid))         (uncontracted)
//   cur   = fadd(fmul(rw, rv), fmul(tw, tv))        (UNcontracted)
//   mp    = fma(beta, m, cur); ms = fadd(mp,-1); p = (mp>=1)
//   m = p ? ms : mp;  s = p ? 1 : 0
// OOB ref reads exact 0.0f from the zero-padded smem row. cur is computed
// with the identical op sequence -- just on a different warp.
//
// R14: warp specialization. Per block (1 per SM): 2 CHAIN warps (pure serial
// LIF recurrence, ~7 issue/step vs the 12-cyc dependence floor) + 2 PRODUCER
// warps (cur precompute into double-buffered smem tiles + coalesced spike
// dump). Pairwise named-barrier handoff per 128-step tile.

#define NB 32
#define NT 4096
#define ND 256
#define THRESH 1.0f
#define TILE 128
#define NTILES (NT / TILE)
#define TSTRIDE 132                 // floats per tile row (528B, 16B-aligned)
#define SREF_N (NT + 256)           // zero pad: delay<128 + slack

#define CURSZ (32 * TSTRIDE)        // one cur/sp buffer (4224 floats)
#define OFF_SREF 0
#define OFF_STGT SREF_N
#define OFF_CUR  (SREF_N + NT)          // cur[group][buf] : 4 buffers
#define OFF_SP   (OFF_CUR + 4 * CURSZ) // sp [group][buf] : 4 buffers
#define SMEM_FLOATS (OFF_SP + 4 * CURSZ)
#define SMEM_BYTES  (SMEM_FLOATS * 4)   // 168,960 B

__device__ __forceinline__ float softplus_xla(float x) {
    const float u = expf(-fabsf(x));
    return __fadd_rn(fmaxf(x, 0.0f), logf(__fadd_rn(1.0f, u)));
}
__device__ __forceinline__ float sigmoid_xla(float x) {
    return 1.0f / (__fadd_rn(1.0f, expf(-x)));
}
__device__ __forceinline__ void bar64(int id) {
    asm volatile("bar.sync %0, %1;" :: "r"(id), "r"(64) : "memory");
}

__global__ void __launch_bounds__(128, 1)
lif_bank_kernel(const float* __restrict__ ref,
                const float* __restrict__ tgt,
                const int*   __restrict__ delays,
                const float* __restrict__ rw_raw,
                const float* __restrict__ tw_raw,
                const float* __restrict__ beta_raw,
                float* __restrict__ out)
{
    extern __shared__ float smem[];
    float* __restrict__ sref = smem + OFF_SREF;
    float* __restrict__ stgt = smem + OFF_STGT;

    const int tid  = threadIdx.x;
    const int wid  = tid >> 5;
    const int lane = tid & 31;
    const int b    = blockIdx.x >> 2;     // 32 batches
    const int q    = blockIdx.x & 3;      // 4 groups of 64 delays
    const int role = wid >> 1;            // 0 = chain, 1 = producer
    const int g    = wid & 1;             // delay subgroup within block
    const int d    = q * 64 + g * 32 + lane;

    float* __restrict__ curb0 = smem + OFF_CUR + (2 * g + 0) * CURSZ;
    float* __restrict__ curb1 = smem + OFF_CUR + (2 * g + 1) * CURSZ;
    float* __restrict__ spb0  = smem + OFF_SP  + (2 * g + 0) * CURSZ;
    float* __restrict__ spb1  = smem + OFF_SP  + (2 * g + 1) * CURSZ;

    // ---- cooperative staging of ref[b,:] (+zero pad) and tgt[b,:] ----
    {
        const float4* __restrict__ ref4 = (const float4*)(ref + b * NT);
        const float4* __restrict__ tgt4 = (const float4*)(tgt + b * NT);
        float4* sr4 = (float4*)sref;
        float4* st4 = (float4*)stgt;
#pragma unroll 2
        for (int i = tid; i < NT / 4; i += 128) {
            sr4[i] = __ldg(ref4 + i);
            st4[i] = __ldg(tgt4 + i);
        }
        for (int i = NT / 4 + tid; i < SREF_N / 4; i += 128)
            sr4[i] = make_float4(0.f, 0.f, 0.f, 0.f);
    }
    __syncthreads();

    float* out_pooled = out;
    float* out_spk    = out + NB * ND;
    float* out_rw     = out + NB * ND + (size_t)NB * ND * NT;
    float* out_tw     = out_rw + ND;
    float* out_beta   = out_tw + ND;

    const int barid = 1 + g;

    if (role == 1) {
        // ================= PRODUCER warp =================
        const float rw    = softplus_xla(rw_raw[d]);
        const float tw    = softplus_xla(tw_raw[d]);
        const int   delay = delays[d];

        // pre-fill tile 0 into buffer 0
        {
#pragma unroll 4
            for (int tt = 0; tt < TILE; tt += 4) {
                const float4 v = *(const float4*)(stgt + tt);
                const float tv[4] = {v.x, v.y, v.z, v.w};
                float c[4];
#pragma unroll
                for (int j = 0; j < 4; j++) {
                    const float rv = sref[delay + tt + j];
                    c[j] = __fadd_rn(__fmul_rn(rw, rv), __fmul_rn(tw, tv[j]));
                }
                *(float4*)&curb0[lane * TSTRIDE + tt] =
                    make_float4(c[0], c[1], c[2], c[3]);
            }
        }
        bar64(barid);

        for (int k = 0; k < NTILES; k++) {
            // fill cur for tile k+1 into buffer !(k&1)
            if (k + 1 < NTILES) {
                float* curN = (k & 1) ? curb0 : curb1;
                const int t0 = (k + 1) * TILE;
#pragma unroll 4
                for (int tt = 0; tt < TILE; tt += 4) {
                    const float4 v = *(const float4*)(stgt + t0 + tt);
                    const float tv[4] = {v.x, v.y, v.z, v.w};
                    float c[4];
#pragma unroll
                    for (int j = 0; j < 4; j++) {
                        const float rv = sref[delay + t0 + tt + j];
                        c[j] = __fadd_rn(__fmul_rn(rw, rv), __fmul_rn(tw, tv[j]));
                    }
                    *(float4*)&curN[lane * TSTRIDE + tt] =
                        make_float4(c[0], c[1], c[2], c[3]);
                }
            }
            // dump spikes of tile k-1 from buffer !(k&1)
            if (k >= 1) {
                float* spN = (k & 1) ? spb0 : spb1;
                const int t0 = (k - 1) * TILE;
#pragma unroll 2
                for (int r = 0; r < 32; r++) {
                    const float4 w = *(const float4*)&spN[r * TSTRIDE + lane * 4];
                    float* dst = out_spk +
                        (size_t)(b * ND + q * 64 + g * 32 + r) * NT + t0;
                    *(float4*)(dst + lane * 4) = w;
                }
            }
            bar64(barid);
        }

        // final dump: tile NTILES-1 lives in buffer (NTILES-1)&1 = 1
        {
            const int t0 = (NTILES - 1) * TILE;
#pragma unroll 2
            for (int r = 0; r < 32; r++) {
                const float4 w = *(const float4*)&spb1[r * TSTRIDE + lane * 4];
                float* dst = out_spk +
                    (size_t)(b * ND + q * 64 + g * 32 + r) * NT + t0;
                *(float4*)(dst + lane * 4) = w;
            }
        }

        if (b == 0) { out_rw[d] = rw; out_tw[d] = tw; }
    } else {
        // ================= CHAIN warp =================
        const float beta = __fadd_rn(0.7f,
                            __fmul_rn(0.295f, sigmoid_xla(beta_raw[d])));
        float m = 0.0f;
        int   cnt = 0;

        bar64(barid);   // wait for tile-0 cur

        for (int k = 0; k < NTILES; k++) {
            float* __restrict__ curb = (k & 1) ? curb1 : curb0;
            float* __restrict__ spb  = (k & 1) ? spb1  : spb0;

            // prefetch first group, then ping through the tile
            float4 c4 = *(const float4*)&curb[lane * TSTRIDE];
#pragma unroll 4
            for (int tt = 0; tt < TILE; tt += 4) {
                const float4 n4 = *(const float4*)
                    &curb[lane * TSTRIDE + ((tt + 4) & (TILE - 1))];
                const float cu[4] = {c4.x, c4.y, c4.z, c4.w};
                float s[4];
#pragma unroll
                for (int j = 0; j < 4; j++) {
                    const float mp = __fmaf_rn(beta, m, cu[j]);
                    const float ms = __fadd_rn(mp, -THRESH);
                    const bool  p  = (mp >= THRESH);
                    m = p ? ms : mp;
                    s[j] = p ? 1.0f : 0.0f;
                    cnt += p ? 1 : 0;
                }
                *(float4*)&spb[lane * TSTRIDE + tt] =
                    make_float4(s[0], s[1], s[2], s[3]);
                c4 = n4;
            }
            bar64(barid);
        }

        out_pooled[b * ND + d] = (float)cnt * (1.0f / NT);
        if (b == 0) out_beta[d] = beta;
    }
}

extern "C" void kernel_launch(void* const* d_in, const int* in_sizes, int n_in,
                              void* d_out, int out_size)
{
    const float* ref      = (const float*)d_in[0];
    const float* tgt      = (const float*)d_in[1];
    const int*   delays   = (const int*)  d_in[2];
    const float* rw_raw   = (const float*)d_in[3];
    const float* tw_raw   = (const float*)d_in[4];
    const float* beta_raw = (const float*)d_in[5];
    float* out = (float*)d_out;

    cudaFuncSetAttribute(lif_bank_kernel,
                         cudaFuncAttributeMaxDynamicSharedMemorySize,
                         SMEM_BYTES);

    // 128 blocks x 128 threads: per block 2 chain warps + 2 producer warps,
    // one block per SM, each warp on its own SMSP.
    lif_bank_kernel<<<NB * 4, 128, SMEM_BYTES>>>(ref, tgt, delays, rw_raw,
                                                 tw_raw, beta_raw, out);
}

// round 16
// speedup vs baseline: 1.3069x; 1.3063x over previous
#include <cuda_runtime.h>

// CoincidenceLIFBank: B=32 x T=4096 x D=256.
// Output: [0,B*D) pooled | [B*D,+B*D*T) spikes | +D rw | +D tw | +D beta
//
// NUMERICS FROZEN (rel_err 9.894e-4 across R6-R14):
//   rw/tw = max(x,0) + logf(1 + expf(-|x|));  sigmoid = 1/(1+expf(-x))
//   beta  = fadd(0.7, fmul(0.295, sigmoid))         (uncontracted)
//   cur   = fadd(fmul(rw, rv), fmul(tw, tv))        (UNcontracted)
//   mp    = fma(beta, m, cur); ms = fadd(mp,-1); p = (mp>=1)
//   m = p ? ms : mp;  s = p ? 1 : 0
// OOB ref reads exact 0.0f from the zero-padded smem row. Spike count is
// integer-valued fp; regrouping its sum is exact (values < 2^24).
//
// R16 = R12 (best: 56us, 254 regs) + (a) 16-step inner iteration with 4
// rotating fetch buffers at prefetch distance 2 groups, (b) count summed as
// a per-group tree OFF the serial chain. Staging prologue stays fully
// unrolled (the R12 schedule ptxas built around it was the win; R13/R14's
// "lean" variants regressed).

#define NB 32
#define NT 4096
#define ND 256
#define THRESH 1.0f
#define TILE 128
#define TSTRIDE 132          // tile row stride in floats (528B, 16B-aligned)
#define SREF_N (NT + 256)    // zero pad: delay<128 + 24-step prefetch slack

__device__ __forceinline__ float softplus_xla(float x) {
    const float u = expf(-fabsf(x));
    return __fadd_rn(fmaxf(x, 0.0f), logf(__fadd_rn(1.0f, u)));
}
__device__ __forceinline__ float sigmoid_xla(float x) {
    return 1.0f / (__fadd_rn(1.0f, expf(-x)));
}

// load tv/rv for a 4-step group (identical to R12's fetch4)
__device__ __forceinline__ void fetch4(const float* __restrict__ sref,
                                       const float* __restrict__ stgt,
                                       const int delay, const int t,
                                       float* __restrict__ rv,
                                       float* __restrict__ tv)
{
    const float4 v = *(const float4*)(stgt + (t & (NT - 1)));
    tv[0] = v.x; tv[1] = v.y; tv[2] = v.z; tv[3] = v.w;
#pragma unroll
    for (int j = 0; j < 4; j++) rv[j] = sref[delay + t + j];
}

// 4 serial LIF steps (identical arithmetic to R12's lif4); cnt accumulated
// as an exact per-group tree OFF the dependent chain.
__device__ __forceinline__ void lif4(const float rw, const float tw,
                                     const float beta,
                                     const float* __restrict__ rv,
                                     const float* __restrict__ tv,
                                     float& m, float& cnt,
                                     float* __restrict__ sp)
{
#pragma unroll
    for (int j = 0; j < 4; j++) {
        const float cur = __fadd_rn(__fmul_rn(rw, rv[j]), __fmul_rn(tw, tv[j]));
        const float mp  = __fmaf_rn(beta, m, cur);
        const float ms  = __fadd_rn(mp, -THRESH);
        const bool  p   = (mp >= THRESH);
        m = p ? ms : mp;
        sp[j] = p ? 1.0f : 0.0f;
    }
    cnt += __fadd_rn(__fadd_rn(sp[0], sp[1]), __fadd_rn(sp[2], sp[3]));
}

__global__ void __launch_bounds__(32)
lif_bank_kernel(const float* __restrict__ ref,
                const float* __restrict__ tgt,
                const int*   __restrict__ delays,
                const float* __restrict__ rw_raw,
                const float* __restrict__ tw_raw,
                const float* __restrict__ beta_raw,
                float* __restrict__ out)
{
    // 256 single-warp blocks: block -> (b, 32-d group). 8 blocks per b.
    const int lane = threadIdx.x;
    const int b    = blockIdx.x >> 3;
    const int d0   = (blockIdx.x & 7) * 32;
    const int d    = d0 + lane;

    __shared__ float sref[SREF_N];             // ref[b,:] + zero pad
    __shared__ float stgt[NT];                 // tgt[b,:]
    __shared__ float stile[32][TSTRIDE];       // spike transpose tile

    // ---- stage ref + tgt rows (coalesced, FULLY unrolled as in R12) ----
    {
        const float4* __restrict__ ref4 = (const float4*)(ref + b * NT);
        const float4* __restrict__ tgt4 = (const float4*)(tgt + b * NT);
        float4* sr4 = (float4*)sref;
        float4* st4 = (float4*)stgt;
#pragma unroll
        for (int i = 0; i < NT / 128; i++) {
            sr4[lane + 32 * i] = __ldg(ref4 + lane + 32 * i);
            st4[lane + 32 * i] = __ldg(tgt4 + lane + 32 * i);
        }
#pragma unroll
        for (int i = NT / 128; i < SREF_N / 128; i++)
            sr4[lane + 32 * i] = make_float4(0.f, 0.f, 0.f, 0.f);
    }

    // ---- per-bank params (frozen recipe) ----
    const float rw   = softplus_xla(rw_raw[d]);
    const float tw   = softplus_xla(tw_raw[d]);
    const float beta = __fadd_rn(0.7f, __fmul_rn(0.295f, sigmoid_xla(beta_raw[d])));
    const int   delay = delays[d];

    float* out_pooled = out;
    float* out_spk    = out + NB * ND;
    float* out_rw     = out + NB * ND + (size_t)NB * ND * NT;
    float* out_tw     = out_rw + ND;
    float* out_beta   = out_tw + ND;

    float m = 0.0f;
    float cnt = 0.0f;

    __syncwarp();   // staged rows visible warp-wide

    // ---- 4-buffer rotating pipeline, prefetch distance 2 groups ----
    float tvA[4], rvA[4], tvB[4], rvB[4];
    float tvC[4], rvC[4], tvD[4], rvD[4];
    float sp[4];
    fetch4(sref, stgt, delay, 0, rvA, tvA);    // prime groups 0 and 1
    fetch4(sref, stgt, delay, 4, rvB, tvB);

    for (int tile0 = 0; tile0 < NT; tile0 += TILE) {
#pragma unroll 2
        for (int t0 = tile0; t0 < tile0 + TILE; t0 += 16) {
            const int o = t0 - tile0;

            fetch4(sref, stgt, delay, t0 + 8, rvC, tvC);
            lif4(rw, tw, beta, rvA, tvA, m, cnt, sp);
            *(float4*)&stile[lane][o] = make_float4(sp[0], sp[1], sp[2], sp[3]);

            fetch4(sref, stgt, delay, t0 + 12, rvD, tvD);
            lif4(rw, tw, beta, rvB, tvB, m, cnt, sp);
            *(float4*)&stile[lane][o + 4] = make_float4(sp[0], sp[1], sp[2], sp[3]);

            fetch4(sref, stgt, delay, t0 + 16, rvA, tvA);
            lif4(rw, tw, beta, rvC, tvC, m, cnt, sp);
            *(float4*)&stile[lane][o + 8] = make_float4(sp[0], sp[1], sp[2], sp[3]);

            fetch4(sref, stgt, delay, t0 + 20, rvB, tvB);
            lif4(rw, tw, beta, rvD, tvD, m, cnt, sp);
            *(float4*)&stile[lane][o + 12] = make_float4(sp[0], sp[1], sp[2], sp[3]);
        }
        __syncwarp();

        // ---- dump: 32 rows x 512B contiguous STG.128 bursts ----
#pragma unroll 4
        for (int r = 0; r < 32; r++) {
            const float4 w = *(const float4*)&stile[r][lane * 4];
            float* dst = out_spk + (size_t)(b * ND + d0 + r) * NT + tile0;
            *(float4*)(dst + lane * 4) = w;
        }
        __syncwarp();
    }

    out_pooled[b * ND + d] = cnt * (1.0f / NT);

    if (b == 0) {   // blocks 0..7 cover d = 0..255 exactly once
        out_rw[d]   = rw;
        out_tw[d]   = tw;
        out_beta[d] = beta;
    }
}

extern "C" void kernel_launch(void* const* d_in, const int* in_sizes, int n_in,
                              void* d_out, int out_size)
{
    const float* ref      = (const float*)d_in[0];
    const float* tgt      = (const float*)d_in[1];
    const int*   delays   = (const int*)  d_in[2];
    const float* rw_raw   = (const float*)d_in[3];
    const float* tw_raw   = (const float*)d_in[4];
    const float* beta_raw = (const float*)d_in[5];
    float* out = (float*)d_out;

    // 256 single-warp blocks; scan loop touches only smem.
    lif_bank_kernel<<<NB * 8, 32>>>(ref, tgt, delays, rw_raw, tw_raw,
                                    beta_raw, out);
}